// round 15
// baseline (speedup 1.0000x reference)
#include <cuda_runtime.h>
#include <math.h>

#define NTOK 32768
#define NBLK 12              // persistent grid for attn stack (all resident)
#define MCAP 304             // max tokens per dilation (actual: 280/64/139)

// flash/qkv dynamic smem offsets (floats)
#define KOFF   0             // K   [304][68]
#define VOFF   20672         // V   [304][68]
#define POFF   41344         // P   [32][308]  (Y [32][68] aliases after sync)
#define QOFF   51200         // Q   [32][68]
#define WTOFF  53376         // projW^T [64][68]
#define SMEM_FLOATS 57728
#define SMEM_BYTES (SMEM_FLOATS * 4)   // 230,912 B
// qkv-stage aliases (inside K region, dead between stages)
#define WQOFF  0             // qkv W^T [64][196]
#define BOFF   12544         // qkv bias [192]
#define TSOFF  12800         // gathered tokens [32][68]

// ---------------- scratch (static device memory; no allocation) ----------------
__device__ float g_t  [NTOK * 64];
__device__ float g_hT [NTOK * 64];
__device__ float g_qs [NTOK * 64];
__device__ float g_ks [NTOK * 64];
__device__ float g_vs [NTOK * 64];
__device__ int   g_idx3[3 * NTOK];
__device__ int   g_M3[3];
__device__ unsigned g_gen = 0;
__device__ unsigned g_arrive = 0;

// ---------------- software grid barrier ----------------------------------------
__device__ __forceinline__ void grid_bar()
{
    __syncthreads();
    if (threadIdx.x == 0) {
        __threadfence();
        unsigned gen = *(volatile unsigned*)&g_gen;
        if (atomicAdd(&g_arrive, 1u) == NBLK - 1) {
            g_arrive = 0;
            __threadfence();
            atomicAdd(&g_gen, 1u);
        } else {
            while (*(volatile unsigned*)&g_gen == gen) {}
        }
        __threadfence();
    }
    __syncthreads();
}

// ---------------- dilation index build (ss-table, bit-exact vs numpy) ----------
__global__ void __launch_bounds__(256) build_idx_kernel()
{
    __shared__ unsigned char valid[769];
    __shared__ int scan[256];
    int bi  = blockIdx.x;
    int dil = (bi == 0) ? 2 : (bi == 1) ? 4 : 6;
    int* out = g_idx3 + bi * NTOK;
    int tid  = threadIdx.x;
    float fd = (float)dil;

    for (int ss = tid; ss < 769; ss += 256) {
        float d = sqrtf((float)ss);
        valid[ss] = ((fmodf(d, fd) == 0.0f) || (ss == 0)) ? 1 : 0;
    }
    __syncthreads();

    int base = tid * 128;
    unsigned long long fl0 = 0ull, fl1 = 0ull;
    int ccnt = 0;
    for (int j = 0; j < 128; ++j) {
        int n = base + j;
        int zz = (n >> 10) - 16, yy = ((n >> 5) & 31) - 16, xx = (n & 31) - 16;
        int ss = zz*zz + yy*yy + xx*xx;
        if (valid[ss]) {
            if (j < 64) fl0 |= (1ull << j); else fl1 |= (1ull << (j - 64));
            ccnt++;
        }
    }
    scan[tid] = ccnt;
    __syncthreads();
    for (int off = 1; off < 256; off <<= 1) {
        int v = (tid >= off) ? scan[tid - off] : 0;
        __syncthreads();
        scan[tid] += v;
        __syncthreads();
    }
    int pos = scan[tid] - ccnt;
    for (int j = 0; j < 64; ++j)
        if (fl0 & (1ull << j)) out[pos++] = base + j;
    for (int j = 0; j < 64; ++j)
        if (fl1 & (1ull << j)) out[pos++] = base + 64 + j;
    if (tid == 255) g_M3[bi] = scan[255];
}

// ---------------- fused patch conv + pos embed, dual-layout write --------------
__global__ void __launch_bounds__(256) conv_pos_kernel(
    const float* __restrict__ x,
    const float* __restrict__ W,
    const float* __restrict__ b,
    const float* __restrict__ pos)
{
    __shared__ float S[128 * 68];
    int bid = blockIdx.x;
    int z   = bid >> 3, yq = bid & 7;
    int y0  = yq * 4;
    int n0  = z * 1024 + y0 * 32;
    int tid = threadIdx.x;

    #pragma unroll
    for (int j = 0; j < 8; ++j) {
        int e   = tid + 256 * j;
        int r   = e >> 5;
        int c4  = e & 31;
        const float4* src = (const float4*)(x
            + (size_t)(4*z + (r >> 4)) * 16384
            + (4*y0 + (r & 15)) * 128 + c4 * 4);
        *(float4*)&S[r * 128 + c4 * 4] = *src;
    }
    __syncthreads();

    int ch = tid & 63;
    int tg = tid >> 6;
    float w[64];
    {
        const float4* wp = (const float4*)(W + ch * 64);
        #pragma unroll
        for (int i = 0; i < 16; ++i) {
            float4 t4 = wp[i];
            w[4*i] = t4.x; w[4*i+1] = t4.y; w[4*i+2] = t4.z; w[4*i+3] = t4.w;
        }
    }
    float bv = b[ch];
    float acc[32];
    #pragma unroll
    for (int i = 0; i < 32; ++i) acc[i] = bv;

    #pragma unroll
    for (int k4 = 0; k4 < 16; ++k4) {
        int row = (k4 >> 2) * 16 + tg * 4 + (k4 & 3);
        const float4* Pr = (const float4*)&S[row * 128];
        float wx = w[4*k4], wy = w[4*k4+1], wz2 = w[4*k4+2], ww = w[4*k4+3];
        #pragma unroll
        for (int i = 0; i < 32; ++i) {
            float4 p = Pr[i];
            acc[i] += p.x * wx;
            acc[i] += p.y * wy;
            acc[i] += p.z * wz2;
            acc[i] += p.w * ww;
        }
    }
    __syncthreads();

    #pragma unroll
    for (int i = 0; i < 32; ++i)
        S[(tg * 32 + i) * 68 + ch] = acc[i];
    __syncthreads();

    #pragma unroll
    for (int rep = 0; rep < 32; ++rep) {
        int e  = tid + 256 * rep;
        int cc = e >> 7, t = e & 127;
        float v = S[t * 68 + cc] + pos[cc * NTOK + n0 + t];
        S[t * 68 + cc] = v;
        g_hT[cc * NTOK + n0 + t] = v;
    }
    __syncthreads();

    #pragma unroll
    for (int j = 0; j < 8; ++j) {
        int e  = tid + 256 * j;
        int t  = e >> 4, c4 = e & 15;
        float4 v = *(const float4*)&S[t * 68 + c4 * 4];
        *(float4*)&g_t[(size_t)(n0 + t) * 64 + c4 * 4] = v;
    }
}

// =================== persistent fused attention stack (round-14, passing) ======
__global__ void __launch_bounds__(1024, 1) fused_attn_kernel(
    const float* __restrict__ qkvw0, const float* __restrict__ qkvb0,
    const float* __restrict__ pw0,   const float* __restrict__ pb0,
    const float* __restrict__ qkvw1, const float* __restrict__ qkvb1,
    const float* __restrict__ pw1,   const float* __restrict__ pb1,
    const float* __restrict__ qkvw2, const float* __restrict__ qkvb2,
    const float* __restrict__ pw2,   const float* __restrict__ pb2)
{
    extern __shared__ float S[];
    int tid = threadIdx.x;
    int bid = blockIdx.x;

    const float* QW[3] = {qkvw0, qkvw1, qkvw2};
    const float* QB[3] = {qkvb0, qkvb1, qkvb2};
    const float* PW[3] = {pw0, pw1, pw2};
    const float* PB[3] = {pb0, pb1, pb2};

    for (int di = 0; di < 3; ++di) {
        int M = g_M3[di];
        const int* __restrict__ idx = g_idx3 + di * NTOK;
        int mtiles = (M + 31) >> 5;

        // ---------------- stage: QKV (scale 1/8 folded into Q) -----------------
        if (bid < mtiles) {
            for (int j = 0; j < 12; ++j) {
                int e = tid + 1024 * j;
                int oc = e >> 6, k = e & 63;
                S[WQOFF + k * 196 + oc] = QW[di][e];
            }
            if (tid < 192) S[BOFF + tid] = QB[di][tid];
            __syncthreads();

            int oc = tid & 255;
            int rg = tid >> 8;

            for (int mt = bid; mt < mtiles; mt += NBLK) {
                int m0 = mt * 32;
                __syncthreads();
                #pragma unroll
                for (int j = 0; j < 2; ++j) {
                    int e = tid + 1024 * j;
                    int ml = e >> 6, k = e & 63;
                    int m = m0 + ml;
                    S[TSOFF + ml * 68 + k] = (m < M) ? g_t[idx[m] * 64 + k] : 0.f;
                }
                __syncthreads();

                if (oc < 192) {
                    float acc[8];
                    float bv = S[BOFF + oc];
                    #pragma unroll
                    for (int u = 0; u < 8; ++u) acc[u] = bv;
                    #pragma unroll
                    for (int k4 = 0; k4 < 16; ++k4) {
                        float w0 = S[WQOFF + (4*k4+0) * 196 + oc];
                        float w1 = S[WQOFF + (4*k4+1) * 196 + oc];
                        float w2 = S[WQOFF + (4*k4+2) * 196 + oc];
                        float w3 = S[WQOFF + (4*k4+3) * 196 + oc];
                        #pragma unroll
                        for (int u = 0; u < 8; ++u) {
                            float4 t4 = *(const float4*)&S[TSOFF + (rg*8+u) * 68 + k4 * 4];
                            acc[u] += t4.x * w0;
                            acc[u] += t4.y * w1;
                            acc[u] += t4.z * w2;
                            acc[u] += t4.w * w3;
                        }
                    }
                    int mmax = min(32, M - m0);
                    #pragma unroll
                    for (int u = 0; u < 8; ++u) {
                        int ml = rg * 8 + u;
                        if (ml < mmax) {
                            int m = m0 + ml;
                            if      (oc <  64) g_qs[m * 64 + oc]       = acc[u] * 0.125f;
                            else if (oc < 128) g_ks[m * 64 + oc - 64]  = acc[u];
                            else               g_vs[m * 64 + oc - 128] = acc[u];
                        }
                    }
                }
            }
        }
        grid_bar();

        // ---------- stage: full-K-resident flash + proj + resid + scatter ------
        if (bid < mtiles) {
            {
                int nslots = M * 16;
                for (int e = tid; e < nslots; e += 1024) {
                    int nl = e >> 4, c4 = e & 15;
                    *(float4*)&S[KOFF + nl * 68 + c4 * 4] =
                        *(const float4*)(g_ks + nl * 64 + c4 * 4);
                    *(float4*)&S[VOFF + nl * 68 + c4 * 4] =
                        *(const float4*)(g_vs + nl * 64 + c4 * 4);
                }
                #pragma unroll
                for (int j = 0; j < 4; ++j) {
                    int e = tid + 1024 * j;
                    int oc = e >> 6, k = e & 63;
                    S[WTOFF + k * 68 + oc] = PW[di][e];
                }
            }
            __syncthreads();

            int r  = tid >> 5;
            int qq = tid & 31;
            int ch = 2 * qq;

            for (int mt = bid; mt < mtiles; mt += NBLK) {
                int m0 = mt * 32;
                __syncthreads();
                if (tid < 512) {
                    int row = tid >> 4, c4 = tid & 15;
                    int m = m0 + row;
                    *(float4*)&S[QOFF + row * 68 + c4 * 4] =
                        *(const float4*)(g_qs + (size_t)(m < M ? m : m0) * 64 + c4 * 4);
                }
                __syncthreads();

                float sc[10];
                int   nlc[10];
                #pragma unroll
                for (int kk = 0; kk < 10; ++kk) {
                    int nl = qq + 32 * kk;
                    nlc[kk] = (nl < M) ? nl : 0;
                    sc[kk]  = 0.f;
                }
                const float* Qr = S + QOFF + r * 68;
                #pragma unroll
                for (int c4 = 0; c4 < 16; ++c4) {
                    float4 q4 = *(const float4*)(Qr + c4 * 4);
                    #pragma unroll
                    for (int kk = 0; kk < 10; ++kk) {
                        float4 k4 = *(const float4*)&S[KOFF + nlc[kk] * 68 + c4 * 4];
                        sc[kk] += q4.x * k4.x;
                        sc[kk] += q4.y * k4.y;
                        sc[kk] += q4.z * k4.z;
                        sc[kk] += q4.w * k4.w;
                    }
                }

                float tmax = -1e30f;
                #pragma unroll
                for (int kk = 0; kk < 10; ++kk) {
                    if (qq + 32 * kk >= M) sc[kk] = -1e30f;
                    tmax = fmaxf(tmax, sc[kk]);
                }
                #pragma unroll
                for (int o = 1; o < 32; o <<= 1)
                    tmax = fmaxf(tmax, __shfl_xor_sync(0xffffffffu, tmax, o));

                float lsum = 0.f;
                #pragma unroll
                for (int kk = 0; kk < 10; ++kk) {
                    int nl = qq + 32 * kk;
                    if (nl < M) {
                        float p = __expf(sc[kk] - tmax);
                        S[POFF + r * 308 + nl] = p;
                        lsum += p;
                    }
                }
                #pragma unroll
                for (int o = 1; o < 32; o <<= 1)
                    lsum += __shfl_xor_sync(0xffffffffu, lsum, o);
                float inv = 1.0f / lsum;
                __syncwarp();

                float y0 = 0.f, y1 = 0.f;
                const float* Pr = S + POFF + r * 308;
                const float* Vb = S + VOFF + ch;
                int nl = 0;
                #pragma unroll 4
                for (; nl + 4 <= M; nl += 4) {
                    #pragma unroll
                    for (int i = 0; i < 4; ++i) {
                        float p = Pr[nl + i];
                        y0 += p * Vb[(nl + i) * 68];
                        y1 += p * Vb[(nl + i) * 68 + 1];
                    }
                }
                for (; nl < M; ++nl) {
                    float p = Pr[nl];
                    y0 += p * Vb[nl * 68];
                    y1 += p * Vb[nl * 68 + 1];
                }

                __syncthreads();
                S[POFF + r * 68 + ch]     = y0 * inv;
                S[POFF + r * 68 + ch + 1] = y1 * inv;
                __syncthreads();

                int oc = tid & 63;
                int rb = tid >> 6;
                float bv = PB[di][oc];
                int mmax = min(32, M - m0);
                for (int rr = rb; rr < mmax; rr += 16) {
                    float a = bv;
                    #pragma unroll
                    for (int c4 = 0; c4 < 16; ++c4) {
                        float4 y4 = *(const float4*)&S[POFF + rr * 68 + c4 * 4];
                        a += y4.x * S[WTOFF + (4*c4+0) * 68 + oc];
                        a += y4.y * S[WTOFF + (4*c4+1) * 68 + oc];
                        a += y4.z * S[WTOFF + (4*c4+2) * 68 + oc];
                        a += y4.w * S[WTOFF + (4*c4+3) * 68 + oc];
                    }
                    a += S[POFF + rr * 68 + oc];
                    int tok = idx[m0 + rr];
                    g_t [tok * 64 + oc]   = a;
                    g_hT[oc * NTOK + tok] = a;
                }
            }
        }
        if (di < 2) grid_bar();
    }
}

// ---------------- trilinear x4 upsample: hT[c][32^3] -> out[c][128^3] ----------
__global__ void __launch_bounds__(256) upsample_kernel(float* __restrict__ out)
{
    const float S = 31.0f / 127.0f;
    int zo  = blockIdx.x;
    int c   = blockIdx.y;
    int tid = threadIdx.x;

    float pz = (float)zo * S;
    int z0 = (int)pz;
    int z1 = min(z0 + 1, 31);
    float wz = pz - (float)z0;

    __shared__ float F[1024];
    __shared__ float R[128][33];

    const float* p0 = g_hT + c * NTOK + z0 * 1024;
    const float* p1 = g_hT + c * NTOK + z1 * 1024;
    #pragma unroll
    for (int j = 0; j < 4; ++j) {
        int i = tid + 256 * j;
        float a = p0[i];
        F[i] = a + wz * (p1[i] - a);
    }
    __syncthreads();

    int w = tid >> 5, lane = tid & 31;

    #pragma unroll
    for (int j = 0; j < 16; ++j) {
        int yo = j * 8 + w;
        float py = (float)yo * S;
        int y0 = (int)py;
        int y1 = min(y0 + 1, 31);
        float wy = py - (float)y0;
        float a = F[y0 * 32 + lane];
        float b = F[y1 * 32 + lane];
        R[yo][lane] = a + wy * (b - a);
    }
    __syncthreads();

    int   x0[4], x1[4];
    float wx[4];
    #pragma unroll
    for (int j = 0; j < 4; ++j) {
        int xo = lane * 4 + j;
        float px = (float)xo * S;
        x0[j] = (int)px;
        x1[j] = min(x0[j] + 1, 31);
        wx[j] = px - (float)x0[j];
    }

    size_t obase = ((size_t)(c * 128 + zo)) * 16384;
    #pragma unroll
    for (int it = 0; it < 16; ++it) {
        int yo = it * 8 + w;
        const float* Rr = &R[yo][0];
        float4 o;
        #pragma unroll
        for (int j = 0; j < 4; ++j) {
            float r0 = Rr[x0[j]];
            (&o.x)[j] = r0 + wx[j] * (Rr[x1[j]] - r0);
        }
        __stcs((float4*)(out + obase + (size_t)yo * 128 + lane * 4), o);
    }
}

// ---------------- fixup: recompute outputs touched by dirty tokens (idx2) ------
// dirty set = idx2 (idx4, idx6 are subsets: fmod exact => d%4==0 or d%6==0
// implies d%2==0). Identical FP expressions as upsample => identical values;
// overlapping recomputes write identical values (benign).
__global__ void __launch_bounds__(256) fixup_kernel(float* __restrict__ out)
{
    int ti = blockIdx.x;
    if (ti >= g_M3[0]) return;
    int tok = g_idx3[ti];
    int z = tok >> 10, y = (tok >> 5) & 31, x = tok & 31;

    const float S = 31.0f / 127.0f;
    int zstart = (z == 0) ? 0 : ((z - 1) * 127) / 31;
    int zo = zstart + blockIdx.y;
    if (zo > 127) return;
    float pz = (float)zo * S;
    int z0 = (int)pz;
    int z1 = min(z0 + 1, 31);
    if (z0 != z && z1 != z) return;
    float wz = pz - (float)z0;

    // y / x candidate lists (<= 11 each; identical float math as upsample)
    int yo_l[11], xo_l[11];
    int nyo = 0, nxo = 0;
    int ystart = (y == 0) ? 0 : ((y - 1) * 127) / 31;
    #pragma unroll
    for (int j = 0; j < 11; ++j) {
        int yo = ystart + j;
        if (yo > 127) break;
        float py = (float)yo * S;
        int y0 = (int)py, y1 = min(y0 + 1, 31);
        if (y0 == y || y1 == y) yo_l[nyo++] = yo;
    }
    int xstart = (x == 0) ? 0 : ((x - 1) * 127) / 31;
    #pragma unroll
    for (int j = 0; j < 11; ++j) {
        int xo = xstart + j;
        if (xo > 127) break;
        float px = (float)xo * S;
        int x0 = (int)px, x1 = min(x0 + 1, 31);
        if (x0 == x || x1 == x) xo_l[nxo++] = xo;
    }
    int npair = nyo * nxo;
    if (npair == 0) return;

    int c = threadIdx.x & 63;
    int q = threadIdx.x >> 6;
    const float* hz0 = g_hT + (size_t)c * NTOK + z0 * 1024;
    const float* hz1 = g_hT + (size_t)c * NTOK + z1 * 1024;
    size_t obase = ((size_t)(c * 128 + zo)) * 16384;

    for (int p = q; p < npair; p += 4) {
        int yo = yo_l[p / nxo];
        int xo = xo_l[p % nxo];
        float py = (float)yo * S;
        int y0 = (int)py, y1 = min(y0 + 1, 31);
        float wy = py - (float)y0;
        float px = (float)xo * S;
        int x0 = (int)px, x1 = min(x0 + 1, 31);
        float wx = px - (float)x0;

        float a00 = hz0[y0*32 + x0], b00 = hz1[y0*32 + x0];
        float a10 = hz0[y1*32 + x0], b10 = hz1[y1*32 + x0];
        float a01 = hz0[y0*32 + x1], b01 = hz1[y0*32 + x1];
        float a11 = hz0[y1*32 + x1], b11 = hz1[y1*32 + x1];
        float F00 = a00 + wz * (b00 - a00);
        float F10 = a10 + wz * (b10 - a10);
        float F01 = a01 + wz * (b01 - a01);
        float F11 = a11 + wz * (b11 - a11);
        float R0 = F00 + wy * (F10 - F00);
        float R1 = F01 + wy * (F11 - F01);
        out[obase + (size_t)yo * 128 + xo] = R0 + wx * (R1 - R0);
    }
}

// ---------------- launch: fork-join — upsample overlaps attention --------------
extern "C" void kernel_launch(void* const* d_in, const int* in_sizes, int n_in,
                              void* d_out, int out_size)
{
    const float* x       = (const float*)d_in[0];
    const float* w_patch = (const float*)d_in[1];
    const float* b_patch = (const float*)d_in[2];
    const float* pos     = (const float*)d_in[3];
    float* out = (float*)d_out;

    cudaFuncSetAttribute(fused_attn_kernel,
                         cudaFuncAttributeMaxDynamicSharedMemorySize, SMEM_BYTES);

    cudaStream_t side;
    cudaStreamCreateWithFlags(&side, cudaStreamNonBlocking);
    cudaEvent_t ev_fork, ev_join;
    cudaEventCreateWithFlags(&ev_fork, cudaEventDisableTiming);
    cudaEventCreateWithFlags(&ev_join, cudaEventDisableTiming);

    // main stream: idx + conv
    build_idx_kernel<<<3, 256>>>();
    conv_pos_kernel<<<256, 256>>>(x, w_patch, b_patch, pos);

    // fork: clean upsample on side stream (reads g_hT; dirty tokens fixed later)
    cudaEventRecord(ev_fork, 0);
    cudaStreamWaitEvent(side, ev_fork, 0);
    upsample_kernel<<<dim3(128, 64), 256, 0, side>>>(out);
    cudaEventRecord(ev_join, side);

    // main stream: attention stack (concurrent with upsample)
    fused_attn_kernel<<<NBLK, 1024, SMEM_BYTES>>>(
        (const float*)d_in[4],  (const float*)d_in[5],
        (const float*)d_in[6],  (const float*)d_in[7],
        (const float*)d_in[8],  (const float*)d_in[9],
        (const float*)d_in[10], (const float*)d_in[11],
        (const float*)d_in[12], (const float*)d_in[13],
        (const float*)d_in[14], (const float*)d_in[15]);

    // join, then fix outputs that depend on dirty tokens
    cudaStreamWaitEvent(0, ev_join, 0);
    fixup_kernel<<<dim3(MCAP, 11), 256>>>(out);
}

// round 16
// speedup vs baseline: 1.1027x; 1.1027x over previous
#include <cuda_runtime.h>
#include <math.h>

#define NTOK 32768
#define NBLK 12              // attn blocks (0..11) inside mega kernel
#define MCAP 304             // max tokens per dilation (actual: 280/64/139)

// attn dynamic smem offsets (floats)
#define KOFF   0             // K   [304][68]
#define VOFF   20672         // V   [304][68]
#define POFF   41344         // P   [32][308]  (Y [32][68] aliases after sync)
#define QOFF   51200         // Q   [32][68]
#define WTOFF  53376         // projW^T [64][68]
#define SMEM_FLOATS 57728
#define SMEM_BYTES (SMEM_FLOATS * 4)   // 230,912 B
// qkv-stage aliases (inside K region, dead between stages)
#define WQOFF  0             // qkv W^T [64][196]
#define BOFF   12544         // qkv bias [192]
#define TSOFF  12800         // gathered tokens [32][68]
// upsample blocks: per-subgroup region = 5248 floats (F[1024] + R[128][33])

// ---------------- scratch (static device memory; no allocation) ----------------
__device__ float g_t  [NTOK * 64];
__device__ float g_hT [NTOK * 64];
__device__ float g_qs [NTOK * 64];
__device__ float g_ks [NTOK * 64];
__device__ float g_vs [NTOK * 64];
__device__ int   g_idx3[3 * NTOK];
__device__ int   g_M3[3];
__device__ unsigned g_gen = 0;
__device__ unsigned g_arrive = 0;

// ---------------- software barrier among the NBLK attn blocks ------------------
__device__ __forceinline__ void grid_bar()
{
    __syncthreads();
    if (threadIdx.x == 0) {
        __threadfence();
        unsigned gen = *(volatile unsigned*)&g_gen;
        if (atomicAdd(&g_arrive, 1u) == NBLK - 1) {
            g_arrive = 0;
            __threadfence();
            atomicAdd(&g_gen, 1u);
        } else {
            while (*(volatile unsigned*)&g_gen == gen) {}
        }
        __threadfence();
    }
    __syncthreads();
}

// ---------------- dilation index build (ss-table, bit-exact vs numpy) ----------
__global__ void __launch_bounds__(256) build_idx_kernel()
{
    __shared__ unsigned char valid[769];
    __shared__ int scan[256];
    int bi  = blockIdx.x;
    int dil = (bi == 0) ? 2 : (bi == 1) ? 4 : 6;
    int* out = g_idx3 + bi * NTOK;
    int tid  = threadIdx.x;
    float fd = (float)dil;

    for (int ss = tid; ss < 769; ss += 256) {
        float d = sqrtf((float)ss);
        valid[ss] = ((fmodf(d, fd) == 0.0f) || (ss == 0)) ? 1 : 0;
    }
    __syncthreads();

    int base = tid * 128;
    unsigned long long fl0 = 0ull, fl1 = 0ull;
    int ccnt = 0;
    for (int j = 0; j < 128; ++j) {
        int n = base + j;
        int zz = (n >> 10) - 16, yy = ((n >> 5) & 31) - 16, xx = (n & 31) - 16;
        int ss = zz*zz + yy*yy + xx*xx;
        if (valid[ss]) {
            if (j < 64) fl0 |= (1ull << j); else fl1 |= (1ull << (j - 64));
            ccnt++;
        }
    }
    scan[tid] = ccnt;
    __syncthreads();
    for (int off = 1; off < 256; off <<= 1) {
        int v = (tid >= off) ? scan[tid - off] : 0;
        __syncthreads();
        scan[tid] += v;
        __syncthreads();
    }
    int pos = scan[tid] - ccnt;
    for (int j = 0; j < 64; ++j)
        if (fl0 & (1ull << j)) out[pos++] = base + j;
    for (int j = 0; j < 64; ++j)
        if (fl1 & (1ull << j)) out[pos++] = base + 64 + j;
    if (tid == 255) g_M3[bi] = scan[255];
}

// ---------------- fused patch conv + pos embed, dual-layout write --------------
__global__ void __launch_bounds__(256) conv_pos_kernel(
    const float* __restrict__ x,
    const float* __restrict__ W,
    const float* __restrict__ b,
    const float* __restrict__ pos)
{
    __shared__ float S[128 * 68];
    int bid = blockIdx.x;
    int z   = bid >> 3, yq = bid & 7;
    int y0  = yq * 4;
    int n0  = z * 1024 + y0 * 32;
    int tid = threadIdx.x;

    #pragma unroll
    for (int j = 0; j < 8; ++j) {
        int e   = tid + 256 * j;
        int r   = e >> 5;
        int c4  = e & 31;
        const float4* src = (const float4*)(x
            + (size_t)(4*z + (r >> 4)) * 16384
            + (4*y0 + (r & 15)) * 128 + c4 * 4);
        *(float4*)&S[r * 128 + c4 * 4] = *src;
    }
    __syncthreads();

    int ch = tid & 63;
    int tg = tid >> 6;
    float w[64];
    {
        const float4* wp = (const float4*)(W + ch * 64);
        #pragma unroll
        for (int i = 0; i < 16; ++i) {
            float4 t4 = wp[i];
            w[4*i] = t4.x; w[4*i+1] = t4.y; w[4*i+2] = t4.z; w[4*i+3] = t4.w;
        }
    }
    float bv = b[ch];
    float acc[32];
    #pragma unroll
    for (int i = 0; i < 32; ++i) acc[i] = bv;

    #pragma unroll
    for (int k4 = 0; k4 < 16; ++k4) {
        int row = (k4 >> 2) * 16 + tg * 4 + (k4 & 3);
        const float4* Pr = (const float4*)&S[row * 128];
        float wx = w[4*k4], wy = w[4*k4+1], wz2 = w[4*k4+2], ww = w[4*k4+3];
        #pragma unroll
        for (int i = 0; i < 32; ++i) {
            float4 p = Pr[i];
            acc[i] += p.x * wx;
            acc[i] += p.y * wy;
            acc[i] += p.z * wz2;
            acc[i] += p.w * ww;
        }
    }
    __syncthreads();

    #pragma unroll
    for (int i = 0; i < 32; ++i)
        S[(tg * 32 + i) * 68 + ch] = acc[i];
    __syncthreads();

    #pragma unroll
    for (int rep = 0; rep < 32; ++rep) {
        int e  = tid + 256 * rep;
        int cc = e >> 7, t = e & 127;
        float v = S[t * 68 + cc] + pos[cc * NTOK + n0 + t];
        S[t * 68 + cc] = v;
        g_hT[cc * NTOK + n0 + t] = v;
    }
    __syncthreads();

    #pragma unroll
    for (int j = 0; j < 8; ++j) {
        int e  = tid + 256 * j;
        int t  = e >> 4, c4 = e & 15;
        float4 v = *(const float4*)&S[t * 68 + c4 * 4];
        *(float4*)&g_t[(size_t)(n0 + t) * 64 + c4 * 4] = v;
    }
}

// =================== mega kernel: attn (blocks 0-11) || upsample (12-147) ======
__global__ void __launch_bounds__(1024, 1) mega_kernel(
    float* __restrict__ out,
    const float* __restrict__ qkvw0, const float* __restrict__ qkvb0,
    const float* __restrict__ pw0,   const float* __restrict__ pb0,
    const float* __restrict__ qkvw1, const float* __restrict__ qkvb1,
    const float* __restrict__ pw1,   const float* __restrict__ pb1,
    const float* __restrict__ qkvw2, const float* __restrict__ qkvb2,
    const float* __restrict__ pw2,   const float* __restrict__ pb2)
{
    extern __shared__ float S[];
    int tid = threadIdx.x;
    int bid = blockIdx.x;

    if (bid >= NBLK) {
        // ---------------- upsample: 136 blocks x 4 subgroups of 256 ------------
        const float SC = 31.0f / 127.0f;
        int sg = tid >> 8;          // subgroup 0..3
        int t2 = tid & 255;
        float* F = S + sg * 5248;                       // [1024]
        float (*R)[33] = (float(*)[33])(F + 1024);      // [128][33]
        int w = t2 >> 5, lane = t2 & 31;

        int   x0[4], x1[4];
        float wx[4];
        #pragma unroll
        for (int j = 0; j < 4; ++j) {
            int xo = lane * 4 + j;
            float px = (float)xo * SC;
            x0[j] = (int)px;
            x1[j] = min(x0[j] + 1, 31);
            wx[j] = px - (float)x0[j];
        }

        for (int tile = (bid - NBLK) * 4 + sg; tile < 8192; tile += 544) {
            int zo = tile & 127;
            int c  = tile >> 7;

            float pz = (float)zo * SC;
            int z0 = (int)pz;
            int z1 = min(z0 + 1, 31);
            float wz = pz - (float)z0;

            const float* p0 = g_hT + (size_t)c * NTOK + z0 * 1024;
            const float* p1 = g_hT + (size_t)c * NTOK + z1 * 1024;
            #pragma unroll
            for (int j = 0; j < 4; ++j) {
                int i = t2 + 256 * j;
                float a = p0[i];
                F[i] = a + wz * (p1[i] - a);
            }
            asm volatile("bar.sync %0, %1;" :: "r"(sg + 1), "r"(256) : "memory");

            #pragma unroll
            for (int j = 0; j < 16; ++j) {
                int yo = j * 8 + w;
                float py = (float)yo * SC;
                int y0 = (int)py;
                int y1 = min(y0 + 1, 31);
                float wy = py - (float)y0;
                float a = F[y0 * 32 + lane];
                float b = F[y1 * 32 + lane];
                R[yo][lane] = a + wy * (b - a);
            }
            asm volatile("bar.sync %0, %1;" :: "r"(sg + 1), "r"(256) : "memory");

            size_t obase = ((size_t)(c * 128 + zo)) * 16384;
            #pragma unroll
            for (int it = 0; it < 16; ++it) {
                int yo = it * 8 + w;
                const float* Rr = &R[yo][0];
                float4 o;
                #pragma unroll
                for (int j = 0; j < 4; ++j) {
                    float r0 = Rr[x0[j]];
                    (&o.x)[j] = r0 + wx[j] * (Rr[x1[j]] - r0);
                }
                __stcs((float4*)(out + obase + (size_t)yo * 128 + lane * 4), o);
            }
        }
        return;
    }

    // ---------------- attention stack (blocks 0..11; round-14 code) ------------
    const float* QW[3] = {qkvw0, qkvw1, qkvw2};
    const float* QB[3] = {qkvb0, qkvb1, qkvb2};
    const float* PW[3] = {pw0, pw1, pw2};
    const float* PB[3] = {pb0, pb1, pb2};

    for (int di = 0; di < 3; ++di) {
        int M = g_M3[di];
        const int* __restrict__ idx = g_idx3 + di * NTOK;
        int mtiles = (M + 31) >> 5;

        // ---------------- stage: QKV (scale 1/8 folded into Q) -----------------
        if (bid < mtiles) {
            for (int j = 0; j < 12; ++j) {
                int e = tid + 1024 * j;
                int oc = e >> 6, k = e & 63;
                S[WQOFF + k * 196 + oc] = QW[di][e];
            }
            if (tid < 192) S[BOFF + tid] = QB[di][tid];
            __syncthreads();

            int oc = tid & 255;
            int rg = tid >> 8;

            for (int mt = bid; mt < mtiles; mt += NBLK) {
                int m0 = mt * 32;
                __syncthreads();
                #pragma unroll
                for (int j = 0; j < 2; ++j) {
                    int e = tid + 1024 * j;
                    int ml = e >> 6, k = e & 63;
                    int m = m0 + ml;
                    S[TSOFF + ml * 68 + k] = (m < M) ? g_t[idx[m] * 64 + k] : 0.f;
                }
                __syncthreads();

                if (oc < 192) {
                    float acc[8];
                    float bv = S[BOFF + oc];
                    #pragma unroll
                    for (int u = 0; u < 8; ++u) acc[u] = bv;
                    #pragma unroll
                    for (int k4 = 0; k4 < 16; ++k4) {
                        float w0 = S[WQOFF + (4*k4+0) * 196 + oc];
                        float w1 = S[WQOFF + (4*k4+1) * 196 + oc];
                        float w2 = S[WQOFF + (4*k4+2) * 196 + oc];
                        float w3 = S[WQOFF + (4*k4+3) * 196 + oc];
                        #pragma unroll
                        for (int u = 0; u < 8; ++u) {
                            float4 t4 = *(const float4*)&S[TSOFF + (rg*8+u) * 68 + k4 * 4];
                            acc[u] += t4.x * w0;
                            acc[u] += t4.y * w1;
                            acc[u] += t4.z * w2;
                            acc[u] += t4.w * w3;
                        }
                    }
                    int mmax = min(32, M - m0);
                    #pragma unroll
                    for (int u = 0; u < 8; ++u) {
                        int ml = rg * 8 + u;
                        if (ml < mmax) {
                            int m = m0 + ml;
                            if      (oc <  64) g_qs[m * 64 + oc]       = acc[u] * 0.125f;
                            else if (oc < 128) g_ks[m * 64 + oc - 64]  = acc[u];
                            else               g_vs[m * 64 + oc - 128] = acc[u];
                        }
                    }
                }
            }
        }
        grid_bar();

        // ---------- stage: full-K-resident flash + proj + resid + scatter ------
        if (bid < mtiles) {
            {
                int nslots = M * 16;
                for (int e = tid; e < nslots; e += 1024) {
                    int nl = e >> 4, c4 = e & 15;
                    *(float4*)&S[KOFF + nl * 68 + c4 * 4] =
                        *(const float4*)(g_ks + nl * 64 + c4 * 4);
                    *(float4*)&S[VOFF + nl * 68 + c4 * 4] =
                        *(const float4*)(g_vs + nl * 64 + c4 * 4);
                }
                #pragma unroll
                for (int j = 0; j < 4; ++j) {
                    int e = tid + 1024 * j;
                    int oc = e >> 6, k = e & 63;
                    S[WTOFF + k * 68 + oc] = PW[di][e];
                }
            }
            __syncthreads();

            int r  = tid >> 5;
            int qq = tid & 31;
            int ch = 2 * qq;

            for (int mt = bid; mt < mtiles; mt += NBLK) {
                int m0 = mt * 32;
                __syncthreads();
                if (tid < 512) {
                    int row = tid >> 4, c4 = tid & 15;
                    int m = m0 + row;
                    *(float4*)&S[QOFF + row * 68 + c4 * 4] =
                        *(const float4*)(g_qs + (size_t)(m < M ? m : m0) * 64 + c4 * 4);
                }
                __syncthreads();

                float sc[10];
                int   nlc[10];
                #pragma unroll
                for (int kk = 0; kk < 10; ++kk) {
                    int nl = qq + 32 * kk;
                    nlc[kk] = (nl < M) ? nl : 0;
                    sc[kk]  = 0.f;
                }
                const float* Qr = S + QOFF + r * 68;
                #pragma unroll
                for (int c4 = 0; c4 < 16; ++c4) {
                    float4 q4 = *(const float4*)(Qr + c4 * 4);
                    #pragma unroll
                    for (int kk = 0; kk < 10; ++kk) {
                        float4 k4 = *(const float4*)&S[KOFF + nlc[kk] * 68 + c4 * 4];
                        sc[kk] += q4.x * k4.x;
                        sc[kk] += q4.y * k4.y;
                        sc[kk] += q4.z * k4.z;
                        sc[kk] += q4.w * k4.w;
                    }
                }

                float tmax = -1e30f;
                #pragma unroll
                for (int kk = 0; kk < 10; ++kk) {
                    if (qq + 32 * kk >= M) sc[kk] = -1e30f;
                    tmax = fmaxf(tmax, sc[kk]);
                }
                #pragma unroll
                for (int o = 1; o < 32; o <<= 1)
                    tmax = fmaxf(tmax, __shfl_xor_sync(0xffffffffu, tmax, o));

                float lsum = 0.f;
                #pragma unroll
                for (int kk = 0; kk < 10; ++kk) {
                    int nl = qq + 32 * kk;
                    if (nl < M) {
                        float p = __expf(sc[kk] - tmax);
                        S[POFF + r * 308 + nl] = p;
                        lsum += p;
                    }
                }
                #pragma unroll
                for (int o = 1; o < 32; o <<= 1)
                    lsum += __shfl_xor_sync(0xffffffffu, lsum, o);
                float inv = 1.0f / lsum;
                __syncwarp();

                float y0 = 0.f, y1 = 0.f;
                const float* Pr = S + POFF + r * 308;
                const float* Vb = S + VOFF + ch;
                int nl = 0;
                #pragma unroll 4
                for (; nl + 4 <= M; nl += 4) {
                    #pragma unroll
                    for (int i = 0; i < 4; ++i) {
                        float p = Pr[nl + i];
                        y0 += p * Vb[(nl + i) * 68];
                        y1 += p * Vb[(nl + i) * 68 + 1];
                    }
                }
                for (; nl < M; ++nl) {
                    float p = Pr[nl];
                    y0 += p * Vb[nl * 68];
                    y1 += p * Vb[nl * 68 + 1];
                }

                __syncthreads();
                S[POFF + r * 68 + ch]     = y0 * inv;
                S[POFF + r * 68 + ch + 1] = y1 * inv;
                __syncthreads();

                int oc = tid & 63;
                int rb = tid >> 6;
                float bv = PB[di][oc];
                int mmax = min(32, M - m0);
                for (int rr = rb; rr < mmax; rr += 16) {
                    float a = bv;
                    #pragma unroll
                    for (int c4 = 0; c4 < 16; ++c4) {
                        float4 y4 = *(const float4*)&S[POFF + rr * 68 + c4 * 4];
                        a += y4.x * S[WTOFF + (4*c4+0) * 68 + oc];
                        a += y4.y * S[WTOFF + (4*c4+1) * 68 + oc];
                        a += y4.z * S[WTOFF + (4*c4+2) * 68 + oc];
                        a += y4.w * S[WTOFF + (4*c4+3) * 68 + oc];
                    }
                    a += S[POFF + rr * 68 + oc];
                    int tok = idx[m0 + rr];
                    g_t [tok * 64 + oc]   = a;
                    g_hT[oc * NTOK + tok] = a;
                }
            }
        }
        if (di < 2) grid_bar();
    }
}

// ---------------- fixup: recompute outputs touched by dirty tokens (idx2) ------
// dirty set = idx2 (idx4, idx6 are subsets: fmod exact). Identical FP
// expressions as upsample => identical values; overlaps benign.
__global__ void __launch_bounds__(256) fixup_kernel(float* __restrict__ out)
{
    int ti = blockIdx.x;
    if (ti >= g_M3[0]) return;
    int tok = g_idx3[ti];
    int z = tok >> 10, y = (tok >> 5) & 31, x = tok & 31;

    const float S = 31.0f / 127.0f;
    int zstart = (z == 0) ? 0 : ((z - 1) * 127) / 31;
    int zo = zstart + blockIdx.y;
    if (zo > 127) return;
    float pz = (float)zo * S;
    int z0 = (int)pz;
    int z1 = min(z0 + 1, 31);
    if (z0 != z && z1 != z) return;
    float wz = pz - (float)z0;

    int yo_l[11], xo_l[11];
    int nyo = 0, nxo = 0;
    int ystart = (y == 0) ? 0 : ((y - 1) * 127) / 31;
    #pragma unroll
    for (int j = 0; j < 11; ++j) {
        int yo = ystart + j;
        if (yo > 127) break;
        float py = (float)yo * S;
        int y0 = (int)py, y1 = min(y0 + 1, 31);
        if (y0 == y || y1 == y) yo_l[nyo++] = yo;
    }
    int xstart = (x == 0) ? 0 : ((x - 1) * 127) / 31;
    #pragma unroll
    for (int j = 0; j < 11; ++j) {
        int xo = xstart + j;
        if (xo > 127) break;
        float px = (float)xo * S;
        int x0 = (int)px, x1 = min(x0 + 1, 31);
        if (x0 == x || x1 == x) xo_l[nxo++] = xo;
    }
    int npair = nyo * nxo;
    if (npair == 0) return;

    int c = threadIdx.x & 63;
    int q = threadIdx.x >> 6;
    const float* hz0 = g_hT + (size_t)c * NTOK + z0 * 1024;
    const float* hz1 = g_hT + (size_t)c * NTOK + z1 * 1024;
    size_t obase = ((size_t)(c * 128 + zo)) * 16384;

    for (int p = q; p < npair; p += 4) {
        int yo = yo_l[p / nxo];
        int xo = xo_l[p % nxo];
        float py = (float)yo * S;
        int y0 = (int)py, y1 = min(y0 + 1, 31);
        float wy = py - (float)y0;
        float px = (float)xo * S;
        int x0 = (int)px, x1 = min(x0 + 1, 31);
        float wx = px - (float)x0;

        float a00 = hz0[y0*32 + x0], b00 = hz1[y0*32 + x0];
        float a10 = hz0[y1*32 + x0], b10 = hz1[y1*32 + x0];
        float a01 = hz0[y0*32 + x1], b01 = hz1[y0*32 + x1];
        float a11 = hz0[y1*32 + x1], b11 = hz1[y1*32 + x1];
        float F00 = a00 + wz * (b00 - a00);
        float F10 = a10 + wz * (b10 - a10);
        float F01 = a01 + wz * (b01 - a01);
        float F11 = a11 + wz * (b11 - a11);
        float R0 = F00 + wy * (F10 - F00);
        float R1 = F01 + wy * (F11 - F01);
        out[obase + (size_t)yo * 128 + xo] = R0 + wx * (R1 - R0);
    }
}

// ---------------- launch: linear chain, overlap inside mega kernel -------------
extern "C" void kernel_launch(void* const* d_in, const int* in_sizes, int n_in,
                              void* d_out, int out_size)
{
    const float* x       = (const float*)d_in[0];
    const float* w_patch = (const float*)d_in[1];
    const float* b_patch = (const float*)d_in[2];
    const float* pos     = (const float*)d_in[3];
    float* out = (float*)d_out;

    cudaFuncSetAttribute(mega_kernel,
                         cudaFuncAttributeMaxDynamicSharedMemorySize, SMEM_BYTES);

    build_idx_kernel<<<3, 256>>>();
    conv_pos_kernel<<<256, 256>>>(x, w_patch, b_patch, pos);

    mega_kernel<<<148, 1024, SMEM_BYTES>>>(
        out,
        (const float*)d_in[4],  (const float*)d_in[5],
        (const float*)d_in[6],  (const float*)d_in[7],
        (const float*)d_in[8],  (const float*)d_in[9],
        (const float*)d_in[10], (const float*)d_in[11],
        (const float*)d_in[12], (const float*)d_in[13],
        (const float*)d_in[14], (const float*)d_in[15]);

    fixup_kernel<<<dim3(MCAP, 11), 256>>>(out);
}

// round 17
// speedup vs baseline: 2.2677x; 2.0565x over previous
#include <cuda_runtime.h>
#include <math.h>

#define NTOK 32768
#define NBLK 12              // attn blocks (0..11) inside mega kernel
#define MCAP 304             // max tokens per dilation (actual: 280/64/139)

// attn dynamic smem offsets (floats)
#define KOFF   0             // K   [304][68]
#define VOFF   20672         // V   [304][68]
#define POFF   41344         // P   [32][308]  (Y [32][68] aliases after sync)
#define QOFF   51200         // Q   [32][68]
#define WTOFF  53376         // projW^T [64][68]
#define SMEM_FLOATS 57728
#define SMEM_BYTES (SMEM_FLOATS * 4)   // 230,912 B
// qkv-stage aliases (inside K region, dead between stages)
#define WQOFF  0             // qkv W^T [64][196]
#define BOFF   12544         // qkv bias [192]
#define TSOFF  12800         // gathered tokens [32][68]
// upsample blocks: per-subgroup region = 5248 floats (F[1024] + R[128][33])

// ---------------- scratch (static device memory; no allocation) ----------------
__device__ float g_t  [NTOK * 64];
__device__ float g_hT [NTOK * 64];
__device__ float g_qs [NTOK * 64];
__device__ float g_ks [NTOK * 64];
__device__ float g_vs [NTOK * 64];
__device__ int   g_idx3[3 * NTOK];
__device__ int   g_M3[3];
__device__ unsigned g_gen = 0;
__device__ unsigned g_arrive = 0;

// ---------------- software barrier among the NBLK attn blocks ------------------
__device__ __forceinline__ void grid_bar()
{
    __syncthreads();
    if (threadIdx.x == 0) {
        __threadfence();
        unsigned gen = *(volatile unsigned*)&g_gen;
        if (atomicAdd(&g_arrive, 1u) == NBLK - 1) {
            g_arrive = 0;
            __threadfence();
            atomicAdd(&g_gen, 1u);
        } else {
            while (*(volatile unsigned*)&g_gen == gen) {}
        }
        __threadfence();
    }
    __syncthreads();
}

// ---------------- dilation index build (ss-table, bit-exact vs numpy) ----------
__global__ void __launch_bounds__(256) build_idx_kernel()
{
    __shared__ unsigned char valid[769];
    __shared__ int scan[256];
    int bi  = blockIdx.x;
    int dil = (bi == 0) ? 2 : (bi == 1) ? 4 : 6;
    int* out = g_idx3 + bi * NTOK;
    int tid  = threadIdx.x;
    float fd = (float)dil;

    for (int ss = tid; ss < 769; ss += 256) {
        float d = sqrtf((float)ss);
        valid[ss] = ((fmodf(d, fd) == 0.0f) || (ss == 0)) ? 1 : 0;
    }
    __syncthreads();

    int base = tid * 128;
    unsigned long long fl0 = 0ull, fl1 = 0ull;
    int ccnt = 0;
    for (int j = 0; j < 128; ++j) {
        int n = base + j;
        int zz = (n >> 10) - 16, yy = ((n >> 5) & 31) - 16, xx = (n & 31) - 16;
        int ss = zz*zz + yy*yy + xx*xx;
        if (valid[ss]) {
            if (j < 64) fl0 |= (1ull << j); else fl1 |= (1ull << (j - 64));
            ccnt++;
        }
    }
    scan[tid] = ccnt;
    __syncthreads();
    for (int off = 1; off < 256; off <<= 1) {
        int v = (tid >= off) ? scan[tid - off] : 0;
        __syncthreads();
        scan[tid] += v;
        __syncthreads();
    }
    int pos = scan[tid] - ccnt;
    for (int j = 0; j < 64; ++j)
        if (fl0 & (1ull << j)) out[pos++] = base + j;
    for (int j = 0; j < 64; ++j)
        if (fl1 & (1ull << j)) out[pos++] = base + 64 + j;
    if (tid == 255) g_M3[bi] = scan[255];
}

// ---------------- fused patch conv + pos embed, dual-layout write --------------
__global__ void __launch_bounds__(256) conv_pos_kernel(
    const float* __restrict__ x,
    const float* __restrict__ W,
    const float* __restrict__ b,
    const float* __restrict__ pos)
{
    __shared__ float S[128 * 68];
    int bid = blockIdx.x;
    int z   = bid >> 3, yq = bid & 7;
    int y0  = yq * 4;
    int n0  = z * 1024 + y0 * 32;
    int tid = threadIdx.x;

    #pragma unroll
    for (int j = 0; j < 8; ++j) {
        int e   = tid + 256 * j;
        int r   = e >> 5;
        int c4  = e & 31;
        const float4* src = (const float4*)(x
            + (size_t)(4*z + (r >> 4)) * 16384
            + (4*y0 + (r & 15)) * 128 + c4 * 4);
        *(float4*)&S[r * 128 + c4 * 4] = *src;
    }
    __syncthreads();

    int ch = tid & 63;
    int tg = tid >> 6;
    float w[64];
    {
        const float4* wp = (const float4*)(W + ch * 64);
        #pragma unroll
        for (int i = 0; i < 16; ++i) {
            float4 t4 = wp[i];
            w[4*i] = t4.x; w[4*i+1] = t4.y; w[4*i+2] = t4.z; w[4*i+3] = t4.w;
        }
    }
    float bv = b[ch];
    float acc[32];
    #pragma unroll
    for (int i = 0; i < 32; ++i) acc[i] = bv;

    #pragma unroll
    for (int k4 = 0; k4 < 16; ++k4) {
        int row = (k4 >> 2) * 16 + tg * 4 + (k4 & 3);
        const float4* Pr = (const float4*)&S[row * 128];
        float wx = w[4*k4], wy = w[4*k4+1], wz2 = w[4*k4+2], ww = w[4*k4+3];
        #pragma unroll
        for (int i = 0; i < 32; ++i) {
            float4 p = Pr[i];
            acc[i] += p.x * wx;
            acc[i] += p.y * wy;
            acc[i] += p.z * wz2;
            acc[i] += p.w * ww;
        }
    }
    __syncthreads();

    #pragma unroll
    for (int i = 0; i < 32; ++i)
        S[(tg * 32 + i) * 68 + ch] = acc[i];
    __syncthreads();

    #pragma unroll
    for (int rep = 0; rep < 32; ++rep) {
        int e  = tid + 256 * rep;
        int cc = e >> 7, t = e & 127;
        float v = S[t * 68 + cc] + pos[cc * NTOK + n0 + t];
        S[t * 68 + cc] = v;
        g_hT[cc * NTOK + n0 + t] = v;
    }
    __syncthreads();

    #pragma unroll
    for (int j = 0; j < 8; ++j) {
        int e  = tid + 256 * j;
        int t  = e >> 4, c4 = e & 15;
        float4 v = *(const float4*)&S[t * 68 + c4 * 4];
        *(float4*)&g_t[(size_t)(n0 + t) * 64 + c4 * 4] = v;
    }
}

// =================== mega kernel: attn (blocks 0-11) || upsample (12-147) ======
__global__ void __launch_bounds__(1024, 1) mega_kernel(
    float* __restrict__ out,
    const float* __restrict__ qkvw0, const float* __restrict__ qkvb0,
    const float* __restrict__ pw0,   const float* __restrict__ pb0,
    const float* __restrict__ qkvw1, const float* __restrict__ qkvb1,
    const float* __restrict__ pw1,   const float* __restrict__ pb1,
    const float* __restrict__ qkvw2, const float* __restrict__ qkvb2,
    const float* __restrict__ pw2,   const float* __restrict__ pb2)
{
    extern __shared__ float S[];
    int tid = threadIdx.x;
    int bid = blockIdx.x;

    if (bid >= NBLK) {
        // ---------------- upsample: 136 blocks x 4 subgroups of 256 ------------
        const float SC = 31.0f / 127.0f;
        int sg = tid >> 8;          // subgroup 0..3
        int t2 = tid & 255;
        float* F = S + sg * 5248;                       // [1024]
        float (*R)[33] = (float(*)[33])(F + 1024);      // [128][33]
        int w = t2 >> 5, lane = t2 & 31;

        int   x0[4], x1[4];
        float wx[4];
        #pragma unroll
        for (int j = 0; j < 4; ++j) {
            int xo = lane * 4 + j;
            float px = (float)xo * SC;
            x0[j] = (int)px;
            x1[j] = min(x0[j] + 1, 31);
            wx[j] = px - (float)x0[j];
        }

        for (int tile = (bid - NBLK) * 4 + sg; tile < 8192; tile += 544) {
            int zo = tile & 127;
            int c  = tile >> 7;

            float pz = (float)zo * SC;
            int z0 = (int)pz;
            int z1 = min(z0 + 1, 31);
            float wz = pz - (float)z0;

            const float* p0 = g_hT + (size_t)c * NTOK + z0 * 1024;
            const float* p1 = g_hT + (size_t)c * NTOK + z1 * 1024;
            #pragma unroll
            for (int j = 0; j < 4; ++j) {
                int i = t2 + 256 * j;
                float a = p0[i];
                F[i] = a + wz * (p1[i] - a);
            }
            asm volatile("bar.sync %0, %1;" :: "r"(sg + 1), "r"(256) : "memory");

            #pragma unroll
            for (int j = 0; j < 16; ++j) {
                int yo = j * 8 + w;
                float py = (float)yo * SC;
                int y0 = (int)py;
                int y1 = min(y0 + 1, 31);
                float wy = py - (float)y0;
                float a = F[y0 * 32 + lane];
                float b = F[y1 * 32 + lane];
                R[yo][lane] = a + wy * (b - a);
            }
            asm volatile("bar.sync %0, %1;" :: "r"(sg + 1), "r"(256) : "memory");

            size_t obase = ((size_t)(c * 128 + zo)) * 16384;
            #pragma unroll
            for (int it = 0; it < 16; ++it) {
                int yo = it * 8 + w;
                const float* Rr = &R[yo][0];
                float4 o;
                #pragma unroll
                for (int j = 0; j < 4; ++j) {
                    float r0 = Rr[x0[j]];
                    (&o.x)[j] = r0 + wx[j] * (Rr[x1[j]] - r0);
                }
                __stcs((float4*)(out + obase + (size_t)yo * 128 + lane * 4), o);
            }
        }
        return;
    }

    // ---------------- attention stack (blocks 0..11; round-14 code) ------------
    const float* QW[3] = {qkvw0, qkvw1, qkvw2};
    const float* QB[3] = {qkvb0, qkvb1, qkvb2};
    const float* PW[3] = {pw0, pw1, pw2};
    const float* PB[3] = {pb0, pb1, pb2};

    for (int di = 0; di < 3; ++di) {
        int M = g_M3[di];
        const int* __restrict__ idx = g_idx3 + di * NTOK;
        int mtiles = (M + 31) >> 5;

        // ---------------- stage: QKV (scale 1/8 folded into Q) -----------------
        if (bid < mtiles) {
            for (int j = 0; j < 12; ++j) {
                int e = tid + 1024 * j;
                int oc = e >> 6, k = e & 63;
                S[WQOFF + k * 196 + oc] = QW[di][e];
            }
            if (tid < 192) S[BOFF + tid] = QB[di][tid];
            __syncthreads();

            int oc = tid & 255;
            int rg = tid >> 8;

            for (int mt = bid; mt < mtiles; mt += NBLK) {
                int m0 = mt * 32;
                __syncthreads();
                #pragma unroll
                for (int j = 0; j < 2; ++j) {
                    int e = tid + 1024 * j;
                    int ml = e >> 6, k = e & 63;
                    int m = m0 + ml;
                    S[TSOFF + ml * 68 + k] = (m < M) ? g_t[idx[m] * 64 + k] : 0.f;
                }
                __syncthreads();

                if (oc < 192) {
                    float acc[8];
                    float bv = S[BOFF + oc];
                    #pragma unroll
                    for (int u = 0; u < 8; ++u) acc[u] = bv;
                    #pragma unroll
                    for (int k4 = 0; k4 < 16; ++k4) {
                        float w0 = S[WQOFF + (4*k4+0) * 196 + oc];
                        float w1 = S[WQOFF + (4*k4+1) * 196 + oc];
                        float w2 = S[WQOFF + (4*k4+2) * 196 + oc];
                        float w3 = S[WQOFF + (4*k4+3) * 196 + oc];
                        #pragma unroll
                        for (int u = 0; u < 8; ++u) {
                            float4 t4 = *(const float4*)&S[TSOFF + (rg*8+u) * 68 + k4 * 4];
                            acc[u] += t4.x * w0;
                            acc[u] += t4.y * w1;
                            acc[u] += t4.z * w2;
                            acc[u] += t4.w * w3;
                        }
                    }
                    int mmax = min(32, M - m0);
                    #pragma unroll
                    for (int u = 0; u < 8; ++u) {
                        int ml = rg * 8 + u;
                        if (ml < mmax) {
                            int m = m0 + ml;
                            if      (oc <  64) g_qs[m * 64 + oc]       = acc[u] * 0.125f;
                            else if (oc < 128) g_ks[m * 64 + oc - 64]  = acc[u];
                            else               g_vs[m * 64 + oc - 128] = acc[u];
                        }
                    }
                }
            }
        }
        grid_bar();

        // ---------- stage: full-K-resident flash + proj + resid + scatter ------
        if (bid < mtiles) {
            {
                int nslots = M * 16;
                for (int e = tid; e < nslots; e += 1024) {
                    int nl = e >> 4, c4 = e & 15;
                    *(float4*)&S[KOFF + nl * 68 + c4 * 4] =
                        *(const float4*)(g_ks + nl * 64 + c4 * 4);
                    *(float4*)&S[VOFF + nl * 68 + c4 * 4] =
                        *(const float4*)(g_vs + nl * 64 + c4 * 4);
                }
                #pragma unroll
                for (int j = 0; j < 4; ++j) {
                    int e = tid + 1024 * j;
                    int oc = e >> 6, k = e & 63;
                    S[WTOFF + k * 68 + oc] = PW[di][e];
                }
            }
            __syncthreads();

            int r  = tid >> 5;
            int qq = tid & 31;
            int ch = 2 * qq;

            for (int mt = bid; mt < mtiles; mt += NBLK) {
                int m0 = mt * 32;
                __syncthreads();
                if (tid < 512) {
                    int row = tid >> 4, c4 = tid & 15;
                    int m = m0 + row;
                    *(float4*)&S[QOFF + row * 68 + c4 * 4] =
                        *(const float4*)(g_qs + (size_t)(m < M ? m : m0) * 64 + c4 * 4);
                }
                __syncthreads();

                float sc[10];
                int   nlc[10];
                #pragma unroll
                for (int kk = 0; kk < 10; ++kk) {
                    int nl = qq + 32 * kk;
                    nlc[kk] = (nl < M) ? nl : 0;
                    sc[kk]  = 0.f;
                }
                const float* Qr = S + QOFF + r * 68;
                #pragma unroll
                for (int c4 = 0; c4 < 16; ++c4) {
                    float4 q4 = *(const float4*)(Qr + c4 * 4);
                    #pragma unroll
                    for (int kk = 0; kk < 10; ++kk) {
                        float4 k4 = *(const float4*)&S[KOFF + nlc[kk] * 68 + c4 * 4];
                        sc[kk] += q4.x * k4.x;
                        sc[kk] += q4.y * k4.y;
                        sc[kk] += q4.z * k4.z;
                        sc[kk] += q4.w * k4.w;
                    }
                }

                float tmax = -1e30f;
                #pragma unroll
                for (int kk = 0; kk < 10; ++kk) {
                    if (qq + 32 * kk >= M) sc[kk] = -1e30f;
                    tmax = fmaxf(tmax, sc[kk]);
                }
                #pragma unroll
                for (int o = 1; o < 32; o <<= 1)
                    tmax = fmaxf(tmax, __shfl_xor_sync(0xffffffffu, tmax, o));

                float lsum = 0.f;
                #pragma unroll
                for (int kk = 0; kk < 10; ++kk) {
                    int nl = qq + 32 * kk;
                    if (nl < M) {
                        float p = __expf(sc[kk] - tmax);
                        S[POFF + r * 308 + nl] = p;
                        lsum += p;
                    }
                }
                #pragma unroll
                for (int o = 1; o < 32; o <<= 1)
                    lsum += __shfl_xor_sync(0xffffffffu, lsum, o);
                float inv = 1.0f / lsum;
                __syncwarp();

                float y0 = 0.f, y1 = 0.f;
                const float* Pr = S + POFF + r * 308;
                const float* Vb = S + VOFF + ch;
                int nl = 0;
                #pragma unroll 4
                for (; nl + 4 <= M; nl += 4) {
                    #pragma unroll
                    for (int i = 0; i < 4; ++i) {
                        float p = Pr[nl + i];
                        y0 += p * Vb[(nl + i) * 68];
                        y1 += p * Vb[(nl + i) * 68 + 1];
                    }
                }
                for (; nl < M; ++nl) {
                    float p = Pr[nl];
                    y0 += p * Vb[nl * 68];
                    y1 += p * Vb[nl * 68 + 1];
                }

                __syncthreads();
                S[POFF + r * 68 + ch]     = y0 * inv;
                S[POFF + r * 68 + ch + 1] = y1 * inv;
                __syncthreads();

                int oc = tid & 63;
                int rb = tid >> 6;
                float bv = PB[di][oc];
                int mmax = min(32, M - m0);
                for (int rr = rb; rr < mmax; rr += 16) {
                    float a = bv;
                    #pragma unroll
                    for (int c4 = 0; c4 < 16; ++c4) {
                        float4 y4 = *(const float4*)&S[POFF + rr * 68 + c4 * 4];
                        a += y4.x * S[WTOFF + (4*c4+0) * 68 + oc];
                        a += y4.y * S[WTOFF + (4*c4+1) * 68 + oc];
                        a += y4.z * S[WTOFF + (4*c4+2) * 68 + oc];
                        a += y4.w * S[WTOFF + (4*c4+3) * 68 + oc];
                    }
                    a += S[POFF + rr * 68 + oc];
                    int tok = idx[m0 + rr];
                    g_t [tok * 64 + oc]   = a;
                    g_hT[oc * NTOK + tok] = a;
                }
            }
        }
        if (di < 2) grid_bar();
    }
}

// ---------------- fixup v2: smem-staged recompute of dirty-dependent outputs ---
// dirty set = idx2 (idx4, idx6 subsets: fmod exact). For one (token, zo) block,
// ALL affected outputs read only a 2x3x3 per-channel neighborhood -> stage it in
// smem once, then compute. FP expressions identical to upsample/validated fixup.
__global__ void __launch_bounds__(256) fixup_kernel(float* __restrict__ out)
{
    int ti = blockIdx.x;
    if (ti >= g_M3[0]) return;
    int tok = g_idx3[ti];
    int z = tok >> 10, y = (tok >> 5) & 31, x = tok & 31;

    const float S = 31.0f / 127.0f;
    int zstart = (z == 0) ? 0 : ((z - 1) * 127) / 31;
    int zo = zstart + blockIdx.y;
    if (zo > 127) return;
    float pz = (float)zo * S;
    int z0 = (int)pz;
    int z1 = min(z0 + 1, 31);
    if (z0 != z && z1 != z) return;
    float wz = pz - (float)z0;

    __shared__ int   yo_l[11], xo_l[11];
    __shared__ int   cnt_s[2];
    __shared__ float IN[64][20];       // [c][zi*9 + iy*3 + ix], padded
    int tid = threadIdx.x;

    if (tid == 0) {
        int nyo = 0;
        int ystart = (y == 0) ? 0 : ((y - 1) * 127) / 31;
        for (int j = 0; j < 11; ++j) {
            int yo = ystart + j;
            if (yo > 127) break;
            float py = (float)yo * S;
            int y0 = (int)py, y1 = min(y0 + 1, 31);
            if (y0 == y || y1 == y) yo_l[nyo++] = yo;
        }
        cnt_s[0] = nyo;
        int nxo = 0;
        int xstart = (x == 0) ? 0 : ((x - 1) * 127) / 31;
        for (int j = 0; j < 11; ++j) {
            int xo = xstart + j;
            if (xo > 127) break;
            float px = (float)xo * S;
            int x0 = (int)px, x1 = min(x0 + 1, 31);
            if (x0 == x || x1 == x) xo_l[nxo++] = xo;
        }
        cnt_s[1] = nxo;
    }

    // stage 2x3x3 neighborhood per channel (clamped rows/cols)
    for (int e = tid; e < 64 * 18; e += 256) {
        int c = e / 18, r2 = e % 18;
        int zi = r2 / 9, yi = (r2 % 9) / 3, xi = r2 % 3;
        int zp = zi ? z1 : z0;
        int yy = min(max(y - 1 + yi, 0), 31);
        int xx = min(max(x - 1 + xi, 0), 31);
        IN[c][zi * 9 + yi * 3 + xi] =
            g_hT[(size_t)c * NTOK + zp * 1024 + yy * 32 + xx];
    }
    __syncthreads();

    int nyo = cnt_s[0], nxo = cnt_s[1];
    int npair = nyo * nxo;
    if (npair == 0) return;

    int c = tid >> 2;                  // 0..63
    int q = tid & 3;
    const float* I = IN[c];

    for (int p = q; p < npair; p += 4) {
        int yo = yo_l[p / nxo];
        int xo = xo_l[p % nxo];
        float py = (float)yo * S;
        int y0 = (int)py, y1 = min(y0 + 1, 31);
        float wy = py - (float)y0;
        float px = (float)xo * S;
        int x0 = (int)px, x1 = min(x0 + 1, 31);
        float wx = px - (float)x0;

        int iy0 = min(max(y0 - (y - 1), 0), 2);
        int iy1 = min(max(y1 - (y - 1), 0), 2);
        int ix0 = min(max(x0 - (x - 1), 0), 2);
        int ix1 = min(max(x1 - (x - 1), 0), 2);

        float a00 = I[iy0*3 + ix0], b00 = I[9 + iy0*3 + ix0];
        float a10 = I[iy1*3 + ix0], b10 = I[9 + iy1*3 + ix0];
        float a01 = I[iy0*3 + ix1], b01 = I[9 + iy0*3 + ix1];
        float a11 = I[iy1*3 + ix1], b11 = I[9 + iy1*3 + ix1];
        float F00 = a00 + wz * (b00 - a00);
        float F10 = a10 + wz * (b10 - a10);
        float F01 = a01 + wz * (b01 - a01);
        float F11 = a11 + wz * (b11 - a11);
        float R0 = F00 + wy * (F10 - F00);
        float R1 = F01 + wy * (F11 - F01);
        out[((size_t)(c * 128 + zo)) * 16384 + (size_t)yo * 128 + xo]
            = R0 + wx * (R1 - R0);
    }
}

// ---------------- launch: linear chain, overlap inside mega kernel -------------
extern "C" void kernel_launch(void* const* d_in, const int* in_sizes, int n_in,
                              void* d_out, int out_size)
{
    const float* x       = (const float*)d_in[0];
    const float* w_patch = (const float*)d_in[1];
    const float* b_patch = (const float*)d_in[2];
    const float* pos     = (const float*)d_in[3];
    float* out = (float*)d_out;

    cudaFuncSetAttribute(mega_kernel,
                         cudaFuncAttributeMaxDynamicSharedMemorySize, SMEM_BYTES);

    build_idx_kernel<<<3, 256>>>();
    conv_pos_kernel<<<256, 256>>>(x, w_patch, b_patch, pos);

    mega_kernel<<<148, 1024, SMEM_BYTES>>>(
        out,
        (const float*)d_in[4],  (const float*)d_in[5],
        (const float*)d_in[6],  (const float*)d_in[7],
        (const float*)d_in[8],  (const float*)d_in[9],
        (const float*)d_in[10], (const float*)d_in[11],
        (const float*)d_in[12], (const float*)d_in[13],
        (const float*)d_in[14], (const float*)d_in[15]);

    fixup_kernel<<<dim3(MCAP, 11), 256>>>(out);
}